// round 2
// baseline (speedup 1.0000x reference)
#include <cuda_runtime.h>
#include <math.h>

// ---------------- problem constants (static shapes) ----------------
#define NTOK   8192          // B*S = 4*2048
#define DIM    1024
#define NEXP   7
#define CAP    2574          // int(8192*2/7*1.1)
#define NSLOTS (NEXP*CAP)    // 18018
#define D4     (DIM/4)       // 256

// ---------------- scratch (static device allocations) ----------------
__device__ float g_exp_h  [NSLOTS * DIM];   // expert hidden
__device__ float g_exp_out[NSLOTS * DIM];   // expert output
__device__ float g_shr_h  [NTOK  * DIM];    // shared-expert hidden
__device__ int   g_tok_exp [NTOK * 2];      // top-2 expert ids per token
__device__ int   g_tok_slot[NTOK * 2];      // slot per pick (-1 = dropped)
__device__ float g_tok_gate[NTOK * 2];      // softmax gate per pick
__device__ int   g_slot_token[NSLOTS];      // token per slot (NTOK = empty)
__device__ float g_gate_sum[NEXP];
__device__ int   g_cnt[NEXP];

// ---------------- init ----------------
__global__ void init_kernel() {
    int i = blockIdx.x * blockDim.x + threadIdx.x;
    if (i < NSLOTS) g_slot_token[i] = NTOK;
    if (i < NEXP) { g_gate_sum[i] = 0.f; g_cnt[i] = 0; }
}

// ---------------- router: 1 warp per token ----------------
__global__ void router_kernel(const float* __restrict__ x,
                              const float* __restrict__ noise,
                              const float* __restrict__ Wr, const float* __restrict__ br,
                              const float* __restrict__ Wn, const float* __restrict__ bn)
{
    int warp = (blockIdx.x * blockDim.x + threadIdx.x) >> 5;
    int lane = threadIdx.x & 31;
    if (warp >= NTOK) return;
    const float* xr = x + (size_t)warp * DIM;

    float ar[NEXP], an[NEXP];
    #pragma unroll
    for (int e = 0; e < NEXP; e++) { ar[e] = 0.f; an[e] = 0.f; }

    for (int d = lane; d < DIM; d += 32) {
        float xv = xr[d];
        #pragma unroll
        for (int e = 0; e < NEXP; e++) {
            ar[e] = fmaf(xv, Wr[d * NEXP + e], ar[e]);
            an[e] = fmaf(xv, Wn[d * NEXP + e], an[e]);
        }
    }
    #pragma unroll
    for (int e = 0; e < NEXP; e++) {
        #pragma unroll
        for (int o = 16; o > 0; o >>= 1) {
            ar[e] += __shfl_xor_sync(0xffffffffu, ar[e], o);
            an[e] += __shfl_xor_sync(0xffffffffu, an[e], o);
        }
    }
    if (lane == 0) {
        float v0 = -INFINITY, v1 = -INFINITY;
        int i0 = 0, i1 = 0;
        #pragma unroll
        for (int e = 0; e < NEXP; e++) {
            float logit = ar[e] + br[e];
            float z = an[e] + bn[e];
            float sp = fmaxf(z, 0.f) + log1pf(expf(-fabsf(z)));      // softplus
            float nv = logit + noise[(size_t)warp * NEXP + e] * sp;
            if (nv > v0) { v1 = v0; i1 = i0; v0 = nv; i0 = e; }
            else if (nv > v1) { v1 = nv; i1 = e; }
        }
        float ed = expf(v1 - v0);
        float p0 = 1.f / (1.f + ed);
        float p1 = ed  / (1.f + ed);
        g_tok_exp [2 * warp]     = i0;
        g_tok_exp [2 * warp + 1] = i1;
        g_tok_gate[2 * warp]     = p0;
        g_tok_gate[2 * warp + 1] = p1;
        atomicAdd(&g_gate_sum[i0], p0);
        atomicAdd(&g_gate_sum[i1], p1);
        atomicAdd(&g_cnt[i0], 1);
        atomicAdd(&g_cnt[i1], 1);
    }
}

// ---------------- dispatch: per-expert FCFS capacity scan ----------------
__global__ void dispatch_kernel()
{
    int e = blockIdx.x;
    int tid = threadIdx.x;
    int lane = tid & 31, wid = tid >> 5;
    __shared__ int wtot[32];
    __shared__ int sbase;
    if (tid == 0) sbase = 0;
    __syncthreads();

    for (int start = 0; start < NTOK; start += 1024) {
        int n = start + tid;
        int e0 = g_tok_exp[2 * n], e1 = g_tok_exp[2 * n + 1];
        int k = (e0 == e) ? 0 : ((e1 == e) ? 1 : -1);
        int m = (k >= 0) ? 1 : 0;

        int v = m;
        #pragma unroll
        for (int o = 1; o < 32; o <<= 1) {
            int t = __shfl_up_sync(0xffffffffu, v, o);
            if (lane >= o) v += t;
        }
        if (lane == 31) wtot[wid] = v;
        __syncthreads();
        if (wid == 0) {
            int t = wtot[lane];
            #pragma unroll
            for (int o = 1; o < 32; o <<= 1) {
                int u = __shfl_up_sync(0xffffffffu, t, o);
                if (lane >= o) t += u;
            }
            wtot[lane] = t;  // inclusive scan of warp totals
        }
        __syncthreads();
        int woff = (wid > 0) ? wtot[wid - 1] : 0;
        int base = sbase;
        int pos = base + woff + v - m;   // exclusive position within expert
        if (m) {
            if (pos < CAP) {
                g_slot_token[e * CAP + pos] = n;
                g_tok_slot[2 * n + k] = pos;
            } else {
                g_tok_slot[2 * n + k] = -1;
            }
        }
        __syncthreads();
        if (tid == 0) sbase += wtot[31];
        __syncthreads();
    }
}

// ---------------- load-balance loss ----------------
__global__ void lbl_kernel(float* __restrict__ out_lbl)
{
    float s = 0.f;
    #pragma unroll
    for (int e = 0; e < NEXP; e++)
        s += (g_gate_sum[e] / (float)NTOK) * ((float)g_cnt[e] / (float)NTOK);
    *out_lbl = (float)NEXP * s;
}

// ---------------- SGEMM 128x128x8, 256 threads, 8x8 per thread ----------------
// MODE 0: shared GEMM1  A=x(param)            C=g_shr_h      M=NTOK relu
// MODE 1: shared GEMM2  A=g_shr_h             C=out(param)   M=NTOK
// MODE 2: expert GEMM1  A=x(param) gathered   C=g_exp_h      M=CAP  relu, batched over z
// MODE 3: expert GEMM2  A=g_exp_h[e]          C=g_exp_out[e] M=CAP  batched over z
template<int MODE>
__global__ __launch_bounds__(256)
void sgemm_kernel(const float* __restrict__ Aparam,
                  const float* __restrict__ Bglob,
                  const float* __restrict__ biasGlob,
                  float* __restrict__ Cparam)
{
    const int e = blockIdx.z;
    const bool RELU = (MODE == 0) || (MODE == 2);
    const int  M    = (MODE <= 1) ? NTOK : CAP;

    const float* A;
    float* C;
    const float* B    = Bglob    + (MODE >= 2 ? (size_t)e * DIM * DIM : 0);
    const float* bias = biasGlob + (MODE >= 2 ? (size_t)e * DIM : 0);
    if (MODE == 0) { A = Aparam;                         C = g_shr_h; }
    if (MODE == 1) { A = g_shr_h;                        C = Cparam; }
    if (MODE == 2) { A = Aparam;                         C = g_exp_h  + (size_t)e * CAP * DIM; }
    if (MODE == 3) { A = g_exp_h + (size_t)e * CAP * DIM; C = g_exp_out + (size_t)e * CAP * DIM; }

    __shared__ float As[8][128];
    __shared__ float Bs[8][128];

    const int row0 = blockIdx.y * 128;
    const int col0 = blockIdx.x * 128;
    const int tid = threadIdx.x;
    const int tx = tid & 15;       // col group
    const int ty = tid >> 4;       // row group

    // A-load mapping: 128 rows x 8 cols = 256 float4
    const int arow = tid >> 1;
    const int acol = (tid & 1) * 4;
    const float* Arow_ptr = 0;
    bool arow_valid = (row0 + arow) < M;
    if (arow_valid) {
        if (MODE == 2) {
            int tokv = g_slot_token[(size_t)e * CAP + row0 + arow];
            if (tokv >= NTOK) arow_valid = false;
            else Arow_ptr = A + (size_t)tokv * DIM;
        } else {
            Arow_ptr = A + (size_t)(row0 + arow) * DIM;
        }
    }
    // B-load mapping: 8 rows x 128 cols = 256 float4
    const int brow = tid >> 5;
    const int bcol = (tid & 31) * 4;

    float acc[8][8];
    #pragma unroll
    for (int i = 0; i < 8; i++)
        #pragma unroll
        for (int j = 0; j < 8; j++) acc[i][j] = 0.f;

    for (int k0 = 0; k0 < DIM; k0 += 8) {
        float4 av = make_float4(0.f, 0.f, 0.f, 0.f);
        if (arow_valid) av = *(const float4*)(Arow_ptr + k0 + acol);
        As[acol + 0][arow] = av.x;
        As[acol + 1][arow] = av.y;
        As[acol + 2][arow] = av.z;
        As[acol + 3][arow] = av.w;

        float4 bv = *(const float4*)(B + (size_t)(k0 + brow) * DIM + col0 + bcol);
        *(float4*)&Bs[brow][bcol] = bv;
        __syncthreads();

        #pragma unroll
        for (int kk = 0; kk < 8; kk++) {
            float a[8], b[8];
            #pragma unroll
            for (int i = 0; i < 8; i++) a[i] = As[kk][ty * 8 + i];
            #pragma unroll
            for (int j = 0; j < 8; j++) b[j] = Bs[kk][tx * 8 + j];
            #pragma unroll
            for (int i = 0; i < 8; i++)
                #pragma unroll
                for (int j = 0; j < 8; j++)
                    acc[i][j] = fmaf(a[i], b[j], acc[i][j]);
        }
        __syncthreads();
    }

    #pragma unroll
    for (int i = 0; i < 8; i++) {
        int r = row0 + ty * 8 + i;
        if (r < M) {
            #pragma unroll
            for (int j = 0; j < 8; j += 4) {
                int c = col0 + tx * 8 + j;
                float4 bb = *(const float4*)(bias + c);
                float4 v;
                v.x = acc[i][j + 0] + bb.x;
                v.y = acc[i][j + 1] + bb.y;
                v.z = acc[i][j + 2] + bb.z;
                v.w = acc[i][j + 3] + bb.w;
                if (RELU) {
                    v.x = fmaxf(v.x, 0.f); v.y = fmaxf(v.y, 0.f);
                    v.z = fmaxf(v.z, 0.f); v.w = fmaxf(v.w, 0.f);
                }
                *(float4*)(C + (size_t)r * DIM + c) = v;
            }
        }
    }
}

// ---------------- combine: out[n] += sum_k gate_k * exp_out[e_k, slot_k] ----------------
__global__ void combine_kernel(float* __restrict__ out)
{
    int i = blockIdx.x * blockDim.x + threadIdx.x;  // over NTOK*D4
    if (i >= NTOK * D4) return;
    int n = i >> 8;       // / D4
    int d = i & (D4 - 1);
    float4 acc = ((float4*)out)[i];
    #pragma unroll
    for (int k = 0; k < 2; k++) {
        int slot = g_tok_slot[2 * n + k];
        if (slot >= 0) {
            int e = g_tok_exp[2 * n + k];
            float g = g_tok_gate[2 * n + k];
            const float4 v = ((const float4*)g_exp_out)[(size_t)(e * CAP + slot) * D4 + d];
            acc.x = fmaf(g, v.x, acc.x);
            acc.y = fmaf(g, v.y, acc.y);
            acc.z = fmaf(g, v.z, acc.z);
            acc.w = fmaf(g, v.w, acc.w);
        }
    }
    ((float4*)out)[i] = acc;
}

// ---------------- launch: ONLY kernel launches (graph-capture safe) ----------------
extern "C" void kernel_launch(void* const* d_in, const int* in_sizes, int n_in,
                              void* d_out, int out_size)
{
    const float* x    = (const float*)d_in[0];
    const float* noise= (const float*)d_in[1];
    const float* Wr   = (const float*)d_in[2];
    const float* br   = (const float*)d_in[3];
    const float* Wn   = (const float*)d_in[4];
    const float* bn   = (const float*)d_in[5];
    const float* W1   = (const float*)d_in[6];
    const float* b1   = (const float*)d_in[7];
    const float* W2   = (const float*)d_in[8];
    const float* b2   = (const float*)d_in[9];
    const float* Ws1  = (const float*)d_in[10];
    const float* bs1  = (const float*)d_in[11];
    const float* Ws2  = (const float*)d_in[12];
    const float* bs2  = (const float*)d_in[13];
    float* out = (float*)d_out;

    // 1. init
    init_kernel<<<(NSLOTS + 255) / 256, 256>>>();
    // 2. router (1 warp/token)
    router_kernel<<<NTOK / 8, 256>>>(x, noise, Wr, br, Wn, bn);
    // 3. dispatch (FCFS capacity)
    dispatch_kernel<<<NEXP, 1024>>>();
    // 4. load-balance loss (scalar appended after the [B,S,D] output)
    if (out_size > NTOK * DIM)
        lbl_kernel<<<1, 1>>>(out + (size_t)NTOK * DIM);

    dim3 blk(256);
    // 5. shared expert GEMM1: g_shr_h = relu(x @ Ws1 + bs1)
    {
        dim3 grid(DIM / 128, NTOK / 128, 1);
        sgemm_kernel<0><<<grid, blk>>>(x, Ws1, bs1, (float*)0);
    }
    // 6. shared expert GEMM2: out = g_shr_h @ Ws2 + bs2
    {
        dim3 grid(DIM / 128, NTOK / 128, 1);
        sgemm_kernel<1><<<grid, blk>>>((const float*)0, Ws2, bs2, out);
    }
    // 7. expert GEMM1 (gather fused): g_exp_h[e] = relu(x[slot_token[e]] @ W1[e] + b1[e])
    {
        dim3 grid(DIM / 128, (CAP + 127) / 128, NEXP);
        sgemm_kernel<2><<<grid, blk>>>(x, W1, b1, (float*)0);
    }
    // 8. expert GEMM2: g_exp_out[e] = g_exp_h[e] @ W2[e] + b2[e]
    {
        dim3 grid(DIM / 128, (CAP + 127) / 128, NEXP);
        sgemm_kernel<3><<<grid, blk>>>((const float*)0, W2, b2, (float*)0);
    }
    // 9. combine (gather, no atomics)
    combine_kernel<<<(NTOK * D4 + 255) / 256, 256>>>(out);
}

// round 6
// speedup vs baseline: 2.3326x; 2.3326x over previous
#include <cuda_runtime.h>
#include <cuda_bf16.h>
#include <math.h>
#include <cstdint>

#define NTOK   8192
#define DIM    1024
#define NEXP   7
#define CAP    2574
#define NSLOTS (NEXP*CAP)
#define D4     (DIM/4)
#define KC     32
#define NCH    (DIM/KC)          // 32
#define MT_CAP ((CAP+127)/128)   // 21

// SMEM: 4 tiles of 128 rows x 80B (32 bf16 + 16B pad), double buffered
#define ROWB       80
#define TILE_B     (128*ROWB)    // 10240
#define OFF_AH     0
#define OFF_AL     (TILE_B)
#define OFF_BH     (2*TILE_B)
#define OFF_BL     (3*TILE_B)
#define STAGE_B    (4*TILE_B)    // 40960
#define SMEM_BYTES (2*STAGE_B)   // 81920

__device__ __nv_bfloat16 g_xs_hi [NTOK*DIM],  g_xs_lo [NTOK*DIM];
__device__ __nv_bfloat16 g_shr_hi[NTOK*DIM],  g_shr_lo[NTOK*DIM];
__device__ __nv_bfloat16 g_exph_hi[NSLOTS*DIM], g_exph_lo[NSLOTS*DIM];
__device__ float         g_exp_out[NSLOTS*DIM];
__device__ __nv_bfloat16 g_wt1_hi[NEXP*DIM*DIM], g_wt1_lo[NEXP*DIM*DIM];
__device__ __nv_bfloat16 g_wt2_hi[NEXP*DIM*DIM], g_wt2_lo[NEXP*DIM*DIM];
__device__ __nv_bfloat16 g_wts1_hi[DIM*DIM], g_wts1_lo[DIM*DIM];
__device__ __nv_bfloat16 g_wts2_hi[DIM*DIM], g_wts2_lo[DIM*DIM];
__device__ int   g_tok_exp [NTOK*2];
__device__ int   g_tok_slot[NTOK*2];
__device__ float g_tok_gate[NTOK*2];
__device__ int   g_slot_token[NSLOTS];
__device__ float g_gate_sum[NEXP];
__device__ int   g_cnt[NEXP];

__device__ __forceinline__ uint32_t smem_u32(const void* p) {
    uint32_t a;
    asm("{ .reg .u64 t; cvta.to.shared.u64 t, %1; cvt.u32.u64 %0, t; }" : "=r"(a) : "l"(p));
    return a;
}
__device__ __forceinline__ void cpa16(uint32_t dst, const void* src, int sz) {
    asm volatile("cp.async.cg.shared.global [%0], [%1], 16, %2;"
                 :: "r"(dst), "l"(src), "r"(sz) : "memory");
}
#define CP_COMMIT() asm volatile("cp.async.commit_group;" ::: "memory")
#define CP_WAIT0()  asm volatile("cp.async.wait_group 0;" ::: "memory")

__device__ __forceinline__ void ldsm4(uint32_t* r, uint32_t addr) {
    asm volatile("ldmatrix.sync.aligned.m8n8.x4.shared.b16 {%0,%1,%2,%3}, [%4];"
                 : "=r"(r[0]), "=r"(r[1]), "=r"(r[2]), "=r"(r[3]) : "r"(addr));
}
__device__ __forceinline__ void mma_bf16(float* d, const uint32_t* a, const uint32_t* b) {
    asm volatile(
        "mma.sync.aligned.m16n8k16.row.col.f32.bf16.bf16.f32 "
        "{%0,%1,%2,%3}, {%4,%5,%6,%7}, {%8,%9}, {%0,%1,%2,%3};"
        : "+f"(d[0]), "+f"(d[1]), "+f"(d[2]), "+f"(d[3])
        : "r"(a[0]), "r"(a[1]), "r"(a[2]), "r"(a[3]), "r"(b[0]), "r"(b[1]));
}

__global__ void init_kernel() {
    int i = blockIdx.x * blockDim.x + threadIdx.x;
    if (i < NSLOTS) g_slot_token[i] = NTOK;
    if (i < NEXP) { g_gate_sum[i] = 0.f; g_cnt[i] = 0; }
}

__global__ void router_kernel(const float* __restrict__ x,
                              const float* __restrict__ noise,
                              const float* __restrict__ Wr, const float* __restrict__ br,
                              const float* __restrict__ Wn, const float* __restrict__ bn)
{
    int warp = (blockIdx.x * blockDim.x + threadIdx.x) >> 5;
    int lane = threadIdx.x & 31;
    if (warp >= NTOK) return;
    const float* xr = x + (size_t)warp * DIM;

    float ar[NEXP], an[NEXP];
    #pragma unroll
    for (int e = 0; e < NEXP; e++) { ar[e] = 0.f; an[e] = 0.f; }
    for (int d = lane; d < DIM; d += 32) {
        float xv = xr[d];
        #pragma unroll
        for (int e = 0; e < NEXP; e++) {
            ar[e] = fmaf(xv, Wr[d * NEXP + e], ar[e]);
            an[e] = fmaf(xv, Wn[d * NEXP + e], an[e]);
        }
    }
    #pragma unroll
    for (int e = 0; e < NEXP; e++) {
        #pragma unroll
        for (int o = 16; o > 0; o >>= 1) {
            ar[e] += __shfl_xor_sync(0xffffffffu, ar[e], o);
            an[e] += __shfl_xor_sync(0xffffffffu, an[e], o);
        }
    }
    if (lane == 0) {
        float v0 = -INFINITY, v1 = -INFINITY;
        int i0 = 0, i1 = 0;
        #pragma unroll
        for (int e = 0; e < NEXP; e++) {
            float logit = ar[e] + br[e];
            float z = an[e] + bn[e];
            float sp = fmaxf(z, 0.f) + log1pf(expf(-fabsf(z)));
            float nv = logit + noise[(size_t)warp * NEXP + e] * sp;
            if (nv > v0) { v1 = v0; i1 = i0; v0 = nv; i0 = e; }
            else if (nv > v1) { v1 = nv; i1 = e; }
        }
        float ed = expf(v1 - v0);
        float p0 = 1.f / (1.f + ed);
        float p1 = ed  / (1.f + ed);
        g_tok_exp [2 * warp]     = i0;
        g_tok_exp [2 * warp + 1] = i1;
        g_tok_gate[2 * warp]     = p0;
        g_tok_gate[2 * warp + 1] = p1;
        atomicAdd(&g_gate_sum[i0], p0);
        atomicAdd(&g_gate_sum[i1], p1);
        atomicAdd(&g_cnt[i0], 1);
        atomicAdd(&g_cnt[i1], 1);
    }
}

__global__ void dispatch_kernel()
{
    int e = blockIdx.x;
    int tid = threadIdx.x;
    int lane = tid & 31, wid = tid >> 5;
    __shared__ int wtot[32];
    __shared__ int sbase;
    if (tid == 0) sbase = 0;
    __syncthreads();

    for (int start = 0; start < NTOK; start += 1024) {
        int n = start + tid;
        int e0 = g_tok_exp[2 * n], e1 = g_tok_exp[2 * n + 1];
        int k = (e0 == e) ? 0 : ((e1 == e) ? 1 : -1);
        int m = (k >= 0) ? 1 : 0;

        int v = m;
        #pragma unroll
        for (int o = 1; o < 32; o <<= 1) {
            int t = __shfl_up_sync(0xffffffffu, v, o);
            if (lane >= o) v += t;
        }
        if (lane == 31) wtot[wid] = v;
        __syncthreads();
        if (wid == 0) {
            int t = wtot[lane];
            #pragma unroll
            for (int o = 1; o < 32; o <<= 1) {
                int u = __shfl_up_sync(0xffffffffu, t, o);
                if (lane >= o) t += u;
            }
            wtot[lane] = t;
        }
        __syncthreads();
        int woff = (wid > 0) ? wtot[wid - 1] : 0;
        int pos = sbase + woff + v - m;
        if (m) {
            if (pos < CAP) {
                g_slot_token[e * CAP + pos] = n;
                g_tok_slot[2 * n + k] = pos;
            } else {
                g_tok_slot[2 * n + k] = -1;
            }
        }
        __syncthreads();
        if (tid == 0) sbase += wtot[31];
        __syncthreads();
    }
}

__global__ void lbl_kernel(float* __restrict__ out_lbl)
{
    float s = 0.f;
    #pragma unroll
    for (int e = 0; e < NEXP; e++)
        s += (g_gate_sum[e] / (float)NTOK) * ((float)g_cnt[e] / (float)NTOK);
    *out_lbl = (float)NEXP * s;
}

__global__ void xsplit_kernel(const float* __restrict__ x)
{
    int i = blockIdx.x * blockDim.x + threadIdx.x;
    if (i >= NTOK * D4) return;
    float4 v = ((const float4*)x)[i];
    __nv_bfloat16 h0 = __float2bfloat16_rn(v.x), h1 = __float2bfloat16_rn(v.y);
    __nv_bfloat16 h2 = __float2bfloat16_rn(v.z), h3 = __float2bfloat16_rn(v.w);
    __nv_bfloat16 l0 = __float2bfloat16_rn(v.x - __bfloat162float(h0));
    __nv_bfloat16 l1 = __float2bfloat16_rn(v.y - __bfloat162float(h1));
    __nv_bfloat16 l2 = __float2bfloat16_rn(v.z - __bfloat162float(h2));
    __nv_bfloat16 l3 = __float2bfloat16_rn(v.w - __bfloat162float(h3));
    __nv_bfloat162 H0(h0, h1), H1(h2, h3), L0(l0, l1), L1(l2, l3);
    ((uint2*)g_xs_hi)[i] = make_uint2(*(uint32_t*)&H0, *(uint32_t*)&H1);
    ((uint2*)g_xs_lo)[i] = make_uint2(*(uint32_t*)&L0, *(uint32_t*)&L1);
}

// WSEL: 0 -> W1 (7 mats), 1 -> W2 (7 mats), 2 -> Ws1, 3 -> Ws2
// transpose [K,N] fp32 -> [N,K] bf16 hi/lo
template<int WSEL>
__global__ void wsplit_kernel(const float* __restrict__ src)
{
    __shared__ float tile[32][33];
    __nv_bfloat16* dhi;
    __nv_bfloat16* dlo;
    if (WSEL == 0) { dhi = g_wt1_hi;  dlo = g_wt1_lo; }
    if (WSEL == 1) { dhi = g_wt2_hi;  dlo = g_wt2_lo; }
    if (WSEL == 2) { dhi = g_wts1_hi; dlo = g_wts1_lo; }
    if (WSEL == 3) { dhi = g_wts2_hi; dlo = g_wts2_lo; }
    int mat = blockIdx.z;
    int k0 = blockIdx.y * 32, n0 = blockIdx.x * 32;
    const float* S = src + (size_t)mat * DIM * DIM;
    int tx = threadIdx.x & 31, ty = threadIdx.x >> 5;
    #pragma unroll
    for (int i = 0; i < 32; i += 8)
        tile[ty + i][tx] = S[(size_t)(k0 + ty + i) * DIM + n0 + tx];
    __syncthreads();
    #pragma unroll
    for (int i = 0; i < 32; i += 8) {
        float v = tile[tx][ty + i];
        __nv_bfloat16 h = __float2bfloat16_rn(v);
        __nv_bfloat16 l = __float2bfloat16_rn(v - __bfloat162float(h));
        size_t o = (size_t)mat * DIM * DIM + (size_t)(n0 + ty + i) * DIM + k0 + tx;
        dhi[o] = h;
        dlo[o] = l;
    }
}

// ---------------- HMMA split-bf16 GEMM: 128x128 tile, 256 thr, warp grid 2x4 ----------------
// MODE 0: shared G1: A=g_xs, B=Wts1 -> g_shr hi/lo (relu), M=NTOK
// MODE 1: shared G2: A=g_shr, B=Wts2 -> f32 Cparam(d_out), M=NTOK
// MODE 2: expert G1: A=g_xs gathered, B=Wt1[e] -> g_exph hi/lo (relu), M=CAP
// MODE 3: expert G2: A=g_exph[e], B=Wt2[e] -> f32 g_exp_out[e], M=CAP
template<int MODE>
__global__ __launch_bounds__(256, 1)
void mgemm_kernel(const float* __restrict__ biasg, float* __restrict__ Cparam)
{
    extern __shared__ char smem[];
    const uint32_t sb = smem_u32(smem);
    const int tid  = threadIdx.x;
    const int wid  = tid >> 5;
    const int lane = tid & 31;
    const int e    = blockIdx.z;
    const int M    = (MODE <= 1) ? NTOK : CAP;
    const int row0 = blockIdx.y * 128;
    const int col0 = blockIdx.x * 128;

    const __nv_bfloat16 *Ahi, *Alo, *Bhi, *Blo;
    const float* bias = biasg + (MODE >= 2 ? (size_t)e * DIM : 0);
    float* Cf = 0;
    __nv_bfloat16 *Chi = 0, *Clo = 0;
    if (MODE == 0) { Ahi = g_xs_hi;  Alo = g_xs_lo;  Bhi = g_wts1_hi; Blo = g_wts1_lo; Chi = g_shr_hi; Clo = g_shr_lo; }
    if (MODE == 1) { Ahi = g_shr_hi; Alo = g_shr_lo; Bhi = g_wts2_hi; Blo = g_wts2_lo; Cf = Cparam; }
    if (MODE == 2) { Ahi = g_xs_hi;  Alo = g_xs_lo;
                     Bhi = g_wt1_hi + (size_t)e * DIM * DIM; Blo = g_wt1_lo + (size_t)e * DIM * DIM;
                     Chi = g_exph_hi + (size_t)e * CAP * DIM; Clo = g_exph_lo + (size_t)e * CAP * DIM; }
    if (MODE == 3) { Ahi = g_exph_hi + (size_t)e * CAP * DIM; Alo = g_exph_lo + (size_t)e * CAP * DIM;
                     Bhi = g_wt2_hi + (size_t)e * DIM * DIM;  Blo = g_wt2_lo + (size_t)e * DIM * DIM;
                     Cf = g_exp_out + (size_t)e * CAP * DIM; }

    // per-thread cp.async mapping: idx = tid + j*256 -> row = idx>>2, c16 = idx&3
    size_t gA[2], gB[2];
    int vA[2];
    uint32_t sO[2];
    #pragma unroll
    for (int j = 0; j < 2; j++) {
        int idx = tid + j * 256;
        int row = idx >> 2, c16 = idx & 3;
        int grow = row0 + row;
        bool valid;
        size_t arow;
        if (MODE == 2) {
            int tok = (grow < CAP) ? g_slot_token[(size_t)e * CAP + grow] : NTOK;
            valid = (tok < NTOK);
            arow = (size_t)(valid ? tok : 0) * DIM;
        } else {
            valid = (grow < M);
            arow = (size_t)(valid ? grow : 0) * DIM;
        }
        vA[j] = valid ? 16 : 0;
        gA[j] = arow + c16 * 8;
        gB[j] = (size_t)(col0 + row) * DIM + c16 * 8;
        sO[j] = (uint32_t)(row * ROWB + c16 * 16);
    }

    float acc[4][4][4];
    #pragma unroll
    for (int mt = 0; mt < 4; mt++)
        #pragma unroll
        for (int nt = 0; nt < 4; nt++)
            #pragma unroll
            for (int q = 0; q < 4; q++) acc[mt][nt][q] = 0.f;

    const int warp_m = wid >> 2, warp_n = wid & 3;
    // ldmatrix lane addressing
    const int rA = warp_m * 64 + (lane & 15);
    const int kA = (lane >> 4) * 8;
    const int rB = warp_n * 32 + (lane & 7) + ((lane >> 4) << 3);
    const int kB = ((lane >> 3) & 1) * 8;

    // prologue: prefetch chunk 0
    {
        uint32_t st = sb;
        #pragma unroll
        for (int j = 0; j < 2; j++) {
            cpa16(st + OFF_AH + sO[j], Ahi + gA[j], vA[j]);
            cpa16(st + OFF_AL + sO[j], Alo + gA[j], vA[j]);
            cpa16(st + OFF_BH + sO[j], Bhi + gB[j], 16);
            cpa16(st + OFF_BL + sO[j], Blo + gB[j], 16);
        }
        CP_COMMIT();
    }

    for (int c = 0; c < NCH; c++) {
        CP_WAIT0();
        __syncthreads();
        if (c + 1 < NCH) {
            uint32_t st = sb + ((c + 1) & 1) * STAGE_B;
            const int k1 = (c + 1) * KC;
            #pragma unroll
            for (int j = 0; j < 2; j++) {
                cpa16(st + OFF_AH + sO[j], Ahi + gA[j] + k1, vA[j]);
                cpa16(st + OFF_AL + sO[j], Alo + gA[j] + k1, vA[j]);
                cpa16(st + OFF_BH + sO[j], Bhi + gB[j] + k1, 16);
                cpa16(st + OFF_BL + sO[j], Blo + gB[j] + k1, 16);
            }
            CP_COMMIT();
        }
        uint32_t st = sb + (c & 1) * STAGE_B;
        #pragma unroll
        for (int ks = 0; ks < 2; ks++) {
            uint32_t ah[4][4], al[4][4], bh[4][2], bl[4][2];
            const int ko = (kA + ks * 16) * 2;
            const int kob = (kB + ks * 16) * 2;
            #pragma unroll
            for (int mt = 0; mt < 4; mt++) {
                uint32_t ra = st + (uint32_t)((rA + mt * 16) * ROWB + ko);
                ldsm4(ah[mt], ra + OFF_AH);
                ldsm4(al[mt], ra + OFF_AL);
            }
            #pragma unroll
            for (int p = 0; p < 2; p++) {
                uint32_t rb = st + (uint32_t)((rB + p * 16) * ROWB + kob);
                uint32_t t[4];
                ldsm4(t, rb + OFF_BH);
                bh[2 * p][0] = t[0]; bh[2 * p][1] = t[1];
                bh[2 * p + 1][0] = t[2]; bh[2 * p + 1][1] = t[3];
                ldsm4(t, rb + OFF_BL);
                bl[2 * p][0] = t[0]; bl[2 * p][1] = t[1];
                bl[2 * p + 1][0] = t[2]; bl[2 * p + 1][1] = t[3];
            }
            #pragma unroll
            for (int mt = 0; mt < 4; mt++)
                #pragma unroll
                for (int nt = 0; nt < 4; nt++) {
                    mma_bf16(acc[mt][nt], ah[mt], bh[nt]);
                    mma_bf16(acc[mt][nt], ah[mt], bl[nt]);
                    mma_bf16(acc[mt][nt], al[mt], bh[nt]);
                }
        }
        __syncthreads();
    }

    // epilogue
    #pragma unroll
    for (int mt = 0; mt < 4; mt++) {
        #pragma unroll
        for (int half = 0; half < 2; half++) {
            int r = row0 + warp_m * 64 + mt * 16 + (lane >> 2) + half * 8;
            if (r < M) {
                #pragma unroll
                for (int nt = 0; nt < 4; nt++) {
                    int cc = col0 + warp_n * 32 + nt * 8 + 2 * (lane & 3);
                    float v0 = acc[mt][nt][2 * half + 0] + bias[cc];
                    float v1 = acc[mt][nt][2 * half + 1] + bias[cc + 1];
                    if (MODE == 0 || MODE == 2) {
                        v0 = fmaxf(v0, 0.f);
                        v1 = fmaxf(v1, 0.f);
                        __nv_bfloat16 h0 = __float2bfloat16_rn(v0);
                        __nv_bfloat16 h1 = __float2bfloat16_rn(v1);
                        __nv_bfloat16 l0 = __float2bfloat16_rn(v0 - __bfloat162float(h0));
                        __nv_bfloat16 l1 = __float2bfloat16_rn(v1 - __bfloat162float(h1));
                        __nv_bfloat162 H(h0, h1), L(l0, l1);
                        *(__nv_bfloat162*)(Chi + (size_t)r * DIM + cc) = H;
                        *(__nv_bfloat162*)(Clo + (size_t)r * DIM + cc) = L;
                    } else {
                        *(float2*)(Cf + (size_t)r * DIM + cc) = make_float2(v0, v1);
                    }
                }
            }
        }
    }
}

__global__ void combine_kernel(float* __restrict__ out)
{
    int i = blockIdx.x * blockDim.x + threadIdx.x;
    if (i >= NTOK * D4) return;
    int n = i >> 8;
    int d = i & (D4 - 1);
    float4 acc = ((float4*)out)[i];
    #pragma unroll
    for (int k = 0; k < 2; k++) {
        int slot = g_tok_slot[2 * n + k];
        if (slot >= 0) {
            int e = g_tok_exp[2 * n + k];
            float g = g_tok_gate[2 * n + k];
            const float4 v = ((const float4*)g_exp_out)[(size_t)(e * CAP + slot) * D4 + d];
            acc.x = fmaf(g, v.x, acc.x);
            acc.y = fmaf(g, v.y, acc.y);
            acc.z = fmaf(g, v.z, acc.z);
            acc.w = fmaf(g, v.w, acc.w);
        }
    }
    ((float4*)out)[i] = acc;
}

extern "C" void kernel_launch(void* const* d_in, const int* in_sizes, int n_in,
                              void* d_out, int out_size)
{
    const float* x    = (const float*)d_in[0];
    const float* noise= (const float*)d_in[1];
    const float* Wr   = (const float*)d_in[2];
    const float* br   = (const float*)d_in[3];
    const float* Wn   = (const float*)d_in[4];
    const float* bn   = (const float*)d_in[5];
    const float* W1   = (const float*)d_in[6];
    const float* b1   = (const float*)d_in[7];
    const float* W2   = (const float*)d_in[8];
    const float* b2   = (const float*)d_in[9];
    const float* Ws1  = (const float*)d_in[10];
    const float* bs1  = (const float*)d_in[11];
    const float* Ws2  = (const float*)d_in[12];
    const float* bs2  = (const float*)d_in[13];
    float* out = (float*)d_out;

    cudaFuncSetAttribute(mgemm_kernel<0>, cudaFuncAttributeMaxDynamicSharedMemorySize, SMEM_BYTES);
    cudaFuncSetAttribute(mgemm_kernel<1>, cudaFuncAttributeMaxDynamicSharedMemorySize, SMEM_BYTES);
    cudaFuncSetAttribute(mgemm_kernel<2>, cudaFuncAttributeMaxDynamicSharedMemorySize, SMEM_BYTES);
    cudaFuncSetAttribute(mgemm_kernel<3>, cudaFuncAttributeMaxDynamicSharedMemorySize, SMEM_BYTES);

    // order chosen so ncu (-s 5 -c 1) profiles the gather expert GEMM (#6)
    init_kernel<<<(NSLOTS + 255) / 256, 256>>>();                          // 1
    router_kernel<<<NTOK / 8, 256>>>(x, noise, Wr, br, Wn, bn);             // 2
    dispatch_kernel<<<NEXP, 1024>>>();                                      // 3
    xsplit_kernel<<<(NTOK * D4 + 255) / 256, 256>>>(x);                     // 4
    wsplit_kernel<0><<<dim3(32, 32, NEXP), 256>>>(W1);                      // 5
    mgemm_kernel<2><<<dim3(8, MT_CAP, NEXP), 256, SMEM_BYTES>>>(b1, 0);     // 6  expert G1
    wsplit_kernel<1><<<dim3(32, 32, NEXP), 256>>>(W2);                      // 7
    mgemm_kernel<3><<<dim3(8, MT_CAP, NEXP), 256, SMEM_BYTES>>>(b2, 0);     // 8  expert G2
    wsplit_kernel<2><<<dim3(32, 32, 1), 256>>>(Ws1);                        // 9
    mgemm_kernel<0><<<dim3(8, NTOK / 128, 1), 256, SMEM_BYTES>>>(bs1, 0);   // 10 shared G1
    wsplit_kernel<3><<<dim3(32, 32, 1), 256>>>(Ws2);                        // 11
    mgemm_kernel<1><<<dim3(8, NTOK / 128, 1), 256, SMEM_BYTES>>>(bs2, out); // 12 shared G2
    if (out_size > NTOK * DIM)
        lbl_kernel<<<1, 1>>>(out + (size_t)NTOK * DIM);                     // 13
    combine_kernel<<<(NTOK * D4 + 255) / 256, 256>>>(out);                  // 14
}

// round 8
// speedup vs baseline: 3.0725x; 1.3172x over previous
#include <cuda_runtime.h>
#include <cuda_fp16.h>
#include <math.h>
#include <cstdint>

#define NTOK   8192
#define DIM    1024
#define NEXP   7
#define CAP    2574
#define NSLOTS (NEXP*CAP)
#define D4     (DIM/4)
#define KC     32
#define NCH    (DIM/KC)          // 32
#define MT_CAP ((CAP+127)/128)   // 21

// SMEM: 3 tiles (A, BH, BL) of 128 rows x 80B, double buffered
#define ROWB       80
#define TILE_B     (128*ROWB)    // 10240
#define OFF_A      0
#define OFF_BH     (TILE_B)
#define OFF_BL     (2*TILE_B)
#define STAGE_B    (3*TILE_B)    // 30720
#define SMEM_BYTES (2*STAGE_B)   // 61440

__device__ __half g_xs  [NTOK*DIM];          // x as fp16 (single limb)
__device__ __half g_shr [NTOK*DIM];          // shared-expert hidden fp16
__device__ __half g_exph[NSLOTS*DIM];        // expert hidden fp16
__device__ float  g_exp_out[NSLOTS*DIM];
__device__ __half g_w1h[NEXP*DIM*DIM], g_w1l[NEXP*DIM*DIM];
__device__ __half g_w2h[NEXP*DIM*DIM], g_w2l[NEXP*DIM*DIM];
__device__ __half g_ws1h[DIM*DIM], g_ws1l[DIM*DIM];
__device__ __half g_ws2h[DIM*DIM], g_ws2l[DIM*DIM];
__device__ int   g_tok_exp [NTOK*2];
__device__ int   g_tok_slot[NTOK*2];
__device__ float g_tok_gate[NTOK*2];
__device__ int   g_slot_token[NSLOTS];
__device__ float g_gate_sum[NEXP];
__device__ int   g_cnt[NEXP];

__device__ __forceinline__ uint32_t smem_u32(const void* p) {
    uint32_t a;
    asm("{ .reg .u64 t; cvta.to.shared.u64 t, %1; cvt.u32.u64 %0, t; }" : "=r"(a) : "l"(p));
    return a;
}
__device__ __forceinline__ void cpa16(uint32_t dst, const void* src, int sz) {
    asm volatile("cp.async.cg.shared.global [%0], [%1], 16, %2;"
                 :: "r"(dst), "l"(src), "r"(sz) : "memory");
}
#define CP_COMMIT() asm volatile("cp.async.commit_group;" ::: "memory")
#define CP_WAIT0()  asm volatile("cp.async.wait_group 0;" ::: "memory")

__device__ __forceinline__ void ldsm4(uint32_t* r, uint32_t addr) {
    asm volatile("ldmatrix.sync.aligned.m8n8.x4.shared.b16 {%0,%1,%2,%3}, [%4];"
                 : "=r"(r[0]), "=r"(r[1]), "=r"(r[2]), "=r"(r[3]) : "r"(addr));
}
__device__ __forceinline__ void mma_f16(float* d, const uint32_t* a, const uint32_t* b) {
    asm volatile(
        "mma.sync.aligned.m16n8k16.row.col.f32.f16.f16.f32 "
        "{%0,%1,%2,%3}, {%4,%5,%6,%7}, {%8,%9}, {%0,%1,%2,%3};"
        : "+f"(d[0]), "+f"(d[1]), "+f"(d[2]), "+f"(d[3])
        : "r"(a[0]), "r"(a[1]), "r"(a[2]), "r"(a[3]), "r"(b[0]), "r"(b[1]));
}

__global__ void init_kernel() {
    int i = blockIdx.x * blockDim.x + threadIdx.x;
    if (i < NSLOTS) g_slot_token[i] = NTOK;
    if (i < NEXP) { g_gate_sum[i] = 0.f; g_cnt[i] = 0; }
}

__global__ void router_kernel(const float* __restrict__ x,
                              const float* __restrict__ noise,
                              const float* __restrict__ Wr, const float* __restrict__ br,
                              const float* __restrict__ Wn, const float* __restrict__ bn)
{
    int warp = (blockIdx.x * blockDim.x + threadIdx.x) >> 5;
    int lane = threadIdx.x & 31;
    if (warp >= NTOK) return;
    const float* xr = x + (size_t)warp * DIM;

    float ar[NEXP], an[NEXP];
    #pragma unroll
    for (int e = 0; e < NEXP; e++) { ar[e] = 0.f; an[e] = 0.f; }
    for (int d = lane; d < DIM; d += 32) {
        float xv = xr[d];
        #pragma unroll
        for (int e = 0; e < NEXP; e++) {
            ar[e] = fmaf(xv, Wr[d * NEXP + e], ar[e]);
            an[e] = fmaf(xv, Wn[d * NEXP + e], an[e]);
        }
    }
    #pragma unroll
    for (int e = 0; e < NEXP; e++) {
        #pragma unroll
        for (int o = 16; o > 0; o >>= 1) {
            ar[e] += __shfl_xor_sync(0xffffffffu, ar[e], o);
            an[e] += __shfl_xor_sync(0xffffffffu, an[e], o);
        }
    }
    if (lane == 0) {
        float v0 = -INFINITY, v1 = -INFINITY;
        int i0 = 0, i1 = 0;
        #pragma unroll
        for (int e = 0; e < NEXP; e++) {
            float logit = ar[e] + br[e];
            float z = an[e] + bn[e];
            float sp = fmaxf(z, 0.f) + log1pf(expf(-fabsf(z)));
            float nv = logit + noise[(size_t)warp * NEXP + e] * sp;
            if (nv > v0) { v1 = v0; i1 = i0; v0 = nv; i0 = e; }
            else if (nv > v1) { v1 = nv; i1 = e; }
        }
        float ed = expf(v1 - v0);
        float p0 = 1.f / (1.f + ed);
        float p1 = ed  / (1.f + ed);
        g_tok_exp [2 * warp]     = i0;
        g_tok_exp [2 * warp + 1] = i1;
        g_tok_gate[2 * warp]     = p0;
        g_tok_gate[2 * warp + 1] = p1;
        atomicAdd(&g_gate_sum[i0], p0);
        atomicAdd(&g_gate_sum[i1], p1);
        atomicAdd(&g_cnt[i0], 1);
        atomicAdd(&g_cnt[i1], 1);
    }
}

__global__ void dispatch_kernel()
{
    int e = blockIdx.x;
    int tid = threadIdx.x;
    int lane = tid & 31, wid = tid >> 5;
    __shared__ int wtot[32];
    __shared__ int sbase;
    if (tid == 0) sbase = 0;
    __syncthreads();

    for (int start = 0; start < NTOK; start += 1024) {
        int n = start + tid;
        int e0 = g_tok_exp[2 * n], e1 = g_tok_exp[2 * n + 1];
        int k = (e0 == e) ? 0 : ((e1 == e) ? 1 : -1);
        int m = (k >= 0) ? 1 : 0;

        int v = m;
        #pragma unroll
        for (int o = 1; o < 32; o <<= 1) {
            int t = __shfl_up_sync(0xffffffffu, v, o);
            if (lane >= o) v += t;
        }
        if (lane == 31) wtot[wid] = v;
        __syncthreads();
        if (wid == 0) {
            int t = wtot[lane];
            #pragma unroll
            for (int o = 1; o < 32; o <<= 1) {
                int u = __shfl_up_sync(0xffffffffu, t, o);
                if (lane >= o) t += u;
            }
            wtot[lane] = t;
        }
        __syncthreads();
        int woff = (wid > 0) ? wtot[wid - 1] : 0;
        int pos = sbase + woff + v - m;
        if (m) {
            if (pos < CAP) {
                g_slot_token[e * CAP + pos] = n;
                g_tok_slot[2 * n + k] = pos;
            } else {
                g_tok_slot[2 * n + k] = -1;
            }
        }
        __syncthreads();
        if (tid == 0) sbase += wtot[31];
        __syncthreads();
    }
}

__global__ void lbl_kernel(float* __restrict__ out_lbl)
{
    float s = 0.f;
    #pragma unroll
    for (int e = 0; e < NEXP; e++)
        s += (g_gate_sum[e] / (float)NTOK) * ((float)g_cnt[e] / (float)NTOK);
    *out_lbl = (float)NEXP * s;
}

// x -> fp16 single limb
__global__ void xsplit_kernel(const float* __restrict__ x)
{
    int i = blockIdx.x * blockDim.x + threadIdx.x;
    if (i >= NTOK * D4) return;
    float4 v = ((const float4*)x)[i];
    __half2 a = __floats2half2_rn(v.x, v.y);
    __half2 b = __floats2half2_rn(v.z, v.w);
    ((uint2*)g_xs)[i] = make_uint2(*(uint32_t*)&a, *(uint32_t*)&b);
}

// transpose [K,N] fp32 -> [N,K] fp16 hi/lo (lo may be subnormal; fp16 HW handles denormals)
template<int WSEL>
__global__ void wsplit_kernel(const float* __restrict__ src)
{
    __shared__ float tile[32][33];
    __half* dhi;
    __half* dlo;
    if (WSEL == 0) { dhi = g_w1h;  dlo = g_w1l; }
    if (WSEL == 1) { dhi = g_w2h;  dlo = g_w2l; }
    if (WSEL == 2) { dhi = g_ws1h; dlo = g_ws1l; }
    if (WSEL == 3) { dhi = g_ws2h; dlo = g_ws2l; }
    int mat = blockIdx.z;
    int k0 = blockIdx.y * 32, n0 = blockIdx.x * 32;
    const float* S = src + (size_t)mat * DIM * DIM;
    int tx = threadIdx.x & 31, ty = threadIdx.x >> 5;
    #pragma unroll
    for (int i = 0; i < 32; i += 8)
        tile[ty + i][tx] = S[(size_t)(k0 + ty + i) * DIM + n0 + tx];
    __syncthreads();
    #pragma unroll
    for (int i = 0; i < 32; i += 8) {
        float v = tile[tx][ty + i];
        __half h = __float2half_rn(v);
        __half l = __float2half_rn(v - __half2float(h));
        size_t o = (size_t)mat * DIM * DIM + (size_t)(n0 + ty + i) * DIM + k0 + tx;
        dhi[o] = h;
        dlo[o] = l;
    }
}

// ---------------- HMMA fp16 2-product GEMM: 128x128 tile, 256 thr, warp grid 2x4 ----------------
// MODE 0: shared G1: A=g_xs, B=Ws1 -> g_shr fp16 (relu), M=NTOK
// MODE 1: shared G2: A=g_shr, B=Ws2 -> f32 Cparam(d_out), M=NTOK
// MODE 2: expert G1: A=g_xs gathered, B=W1[e] -> g_exph fp16 (relu), M=CAP
// MODE 3: expert G2: A=g_exph[e], B=W2[e] -> f32 g_exp_out[e], M=CAP
template<int MODE>
__global__ __launch_bounds__(256, 1)
void mgemm_kernel(const float* __restrict__ biasg, float* __restrict__ Cparam)
{
    extern __shared__ char smem[];
    const uint32_t sb = smem_u32(smem);
    const int tid  = threadIdx.x;
    const int wid  = tid >> 5;
    const int lane = tid & 31;
    const int e    = blockIdx.z;
    const int M    = (MODE <= 1) ? NTOK : CAP;
    const int row0 = blockIdx.y * 128;
    const int col0 = blockIdx.x * 128;

    const __half *A, *Bh, *Bl;
    const float* bias = biasg + (MODE >= 2 ? (size_t)e * DIM : 0);
    float* Cf = 0;
    __half* Ch = 0;
    if (MODE == 0) { A = g_xs;  Bh = g_ws1h; Bl = g_ws1l; Ch = g_shr; }
    if (MODE == 1) { A = g_shr; Bh = g_ws2h; Bl = g_ws2l; Cf = Cparam; }
    if (MODE == 2) { A = g_xs;
                     Bh = g_w1h + (size_t)e * DIM * DIM; Bl = g_w1l + (size_t)e * DIM * DIM;
                     Ch = g_exph + (size_t)e * CAP * DIM; }
    if (MODE == 3) { A = g_exph + (size_t)e * CAP * DIM;
                     Bh = g_w2h + (size_t)e * DIM * DIM;  Bl = g_w2l + (size_t)e * DIM * DIM;
                     Cf = g_exp_out + (size_t)e * CAP * DIM; }

    // per-thread cp.async mapping: idx = tid + j*256 -> row = idx>>2, c16 = idx&3
    size_t gA[2], gB[2];
    int vA[2];
    uint32_t sO[2];
    #pragma unroll
    for (int j = 0; j < 2; j++) {
        int idx = tid + j * 256;
        int row = idx >> 2, c16 = idx & 3;
        int grow = row0 + row;
        bool valid;
        size_t arow;
        if (MODE == 2) {
            int tok = (grow < CAP) ? g_slot_token[(size_t)e * CAP + grow] : NTOK;
            valid = (tok < NTOK);
            arow = (size_t)(valid ? tok : 0) * DIM;
        } else {
            valid = (grow < M);
            arow = (size_t)(valid ? grow : 0) * DIM;
        }
        vA[j] = valid ? 16 : 0;
        gA[j] = arow + c16 * 8;
        gB[j] = (size_t)(col0 + row) * DIM + c16 * 8;
        sO[j] = (uint32_t)(row * ROWB + c16 * 16);
    }

    float acc[4][4][4];
    #pragma unroll
    for (int mt = 0; mt < 4; mt++)
        #pragma unroll
        for (int nt = 0; nt < 4; nt++)
            #pragma unroll
            for (int q = 0; q < 4; q++) acc[mt][nt][q] = 0.f;

    const int warp_m = wid >> 2, warp_n = wid & 3;
    const int rA = warp_m * 64 + (lane & 15);
    const int kA = (lane >> 4) * 8;
    const int rB = warp_n * 32 + (lane & 7) + ((lane >> 4) << 3);
    const int kB = ((lane >> 3) & 1) * 8;

    // prologue: prefetch chunk 0
    {
        uint32_t st = sb;
        #pragma unroll
        for (int j = 0; j < 2; j++) {
            cpa16(st + OFF_A  + sO[j], A  + gA[j], vA[j]);
            cpa16(st + OFF_BH + sO[j], Bh + gB[j], 16);
            cpa16(st + OFF_BL + sO[j], Bl + gB[j], 16);
        }
        CP_COMMIT();
    }

    for (int c = 0; c < NCH; c++) {
        CP_WAIT0();
        __syncthreads();
        if (c + 1 < NCH) {
            uint32_t st = sb + ((c + 1) & 1) * STAGE_B;
            const int k1 = (c + 1) * KC;
            #pragma unroll
            for (int j = 0; j < 2; j++) {
                cpa16(st + OFF_A  + sO[j], A  + gA[j] + k1, vA[j]);
                cpa16(st + OFF_BH + sO[j], Bh + gB[j] + k1, 16);
                cpa16(st + OFF_BL + sO[j], Bl + gB[j] + k1, 16);
            }
            CP_COMMIT();
        }
        uint32_t st = sb + (c & 1) * STAGE_B;
        #pragma unroll
        for (int ks = 0; ks < 2; ks++) {
            uint32_t a[4][4], bh[4][2], bl[4][2];
            const int ko  = (kA + ks * 16) * 2;
            const int kob = (kB + ks * 16) * 2;
            #pragma unroll
            for (int mt = 0; mt < 4; mt++) {
                uint32_t ra = st + (uint32_t)((rA + mt * 16) * ROWB + ko);
                ldsm4(a[mt], ra + OFF_A);
            }
            #pragma unroll
            for (int p = 0; p < 2; p++) {
                uint32_t rb = st + (uint32_t)((rB + p * 16) * ROWB + kob);
                uint32_t t[4];
                ldsm4(t, rb + OFF_BH);
                bh[2 * p][0] = t[0]; bh[2 * p][1] = t[1];
                bh[2 * p + 1][0] = t[2]; bh[2 * p + 1][1] = t[3];
                ldsm4(t, rb + OFF_BL);
                bl[2 * p][0] = t[0]; bl[2 * p][1] = t[1];
                bl[2 * p + 1][0] = t[2]; bl[2 * p + 1][1] = t[3];
            }
            #pragma unroll
            for (int mt = 0; mt < 4; mt++)
                #pragma unroll
                for (int nt = 0; nt < 4; nt++) {
                    mma_f16(acc[mt][nt], a[mt], bh[nt]);
                    mma_f16(acc[mt][nt], a[mt], bl[nt]);
                }
        }
        __syncthreads();
    }

    // epilogue
    #pragma unroll
    for (int mt = 0; mt < 4; mt++) {
        #pragma unroll
        for (int half = 0; half < 2; half++) {
            int r = row0 + warp_m * 64 + mt * 16 + (lane >> 2) + half * 8;
            if (r < M) {
                #pragma unroll
                for (int nt = 0; nt < 4; nt++) {
                    int cc = col0 + warp_n * 32 + nt * 8 + 2 * (lane & 3);
                    float v0 = acc[mt][nt][2 * half + 0] + bias[cc];
                    float v1 = acc[mt][nt][2 * half + 1] + bias[cc + 1];
                    if (MODE == 0 || MODE == 2) {
                        v0 = fmaxf(v0, 0.f);
                        v1 = fmaxf(v1, 0.f);
                        __half2 H = __floats2half2_rn(v0, v1);
                        *(__half2*)(Ch + (size_t)r * DIM + cc) = H;
                    } else {
                        *(float2*)(Cf + (size_t)r * DIM + cc) = make_float2(v0, v1);
                    }
                }
            }
        }
    }
}

__global__ void combine_kernel(float* __restrict__ out)
{
    int i = blockIdx.x * blockDim.x + threadIdx.x;
    if (i >= NTOK * D4) return;
    int n = i >> 8;
    int d = i & (D4 - 1);
    float4 acc = ((float4*)out)[i];
    #pragma unroll
    for (int k = 0; k < 2; k++) {
        int slot = g_tok_slot[2 * n + k];
        if (slot >= 0) {
            int e = g_tok_exp[2 * n + k];
            float g = g_tok_gate[2 * n + k];
            const float4 v = ((const float4*)g_exp_out)[(size_t)(e * CAP + slot) * D4 + d];
            acc.x = fmaf(g, v.x, acc.x);
            acc.y = fmaf(g, v.y, acc.y);
            acc.z = fmaf(g, v.z, acc.z);
            acc.w = fmaf(g, v.w, acc.w);
        }
    }
    ((float4*)out)[i] = acc;
}

extern "C" void kernel_launch(void* const* d_in, const int* in_sizes, int n_in,
                              void* d_out, int out_size)
{
    const float* x    = (const float*)d_in[0];
    const float* noise= (const float*)d_in[1];
    const float* Wr   = (const float*)d_in[2];
    const float* br   = (const float*)d_in[3];
    const float* Wn   = (const float*)d_in[4];
    const float* bn   = (const float*)d_in[5];
    const float* W1   = (const float*)d_in[6];
    const float* b1   = (const float*)d_in[7];
    const float* W2   = (const float*)d_in[8];
    const float* b2   = (const float*)d_in[9];
    const float* Ws1  = (const float*)d_in[10];
    const float* bs1  = (const float*)d_in[11];
    const float* Ws2  = (const float*)d_in[12];
    const float* bs2  = (const float*)d_in[13];
    float* out = (float*)d_out;

    cudaFuncSetAttribute(mgemm_kernel<0>, cudaFuncAttributeMaxDynamicSharedMemorySize, SMEM_BYTES);
    cudaFuncSetAttribute(mgemm_kernel<1>, cudaFuncAttributeMaxDynamicSharedMemorySize, SMEM_BYTES);
    cudaFuncSetAttribute(mgemm_kernel<2>, cudaFuncAttributeMaxDynamicSharedMemorySize, SMEM_BYTES);
    cudaFuncSetAttribute(mgemm_kernel<3>, cudaFuncAttributeMaxDynamicSharedMemorySize, SMEM_BYTES);

    // order chosen so ncu (-s 5 -c 1) profiles the gather expert GEMM (#6)
    init_kernel<<<(NSLOTS + 255) / 256, 256>>>();                          // 1
    router_kernel<<<NTOK / 8, 256>>>(x, noise, Wr, br, Wn, bn);             // 2
    dispatch_kernel<<<NEXP, 1024>>>();                                      // 3
    xsplit_kernel<<<(NTOK * D4 + 255) / 256, 256>>>(x);                     // 4
    wsplit_kernel<0><<<dim3(32, 32, NEXP), 256>>>(W1);                      // 5
    mgemm_kernel<2><<<dim3(8, MT_CAP, NEXP), 256, SMEM_BYTES>>>(b1, 0);     // 6  expert G1
    wsplit_kernel<1><<<dim3(32, 32, NEXP), 256>>>(W2);                      // 7
    mgemm_kernel<3><<<dim3(8, MT_CAP, NEXP), 256, SMEM_BYTES>>>(b2, 0);     // 8  expert G2
    wsplit_kernel<2><<<dim3(32, 32, 1), 256>>>(Ws1);                        // 9
    mgemm_kernel<0><<<dim3(8, NTOK / 128, 1), 256, SMEM_BYTES>>>(bs1, 0);   // 10 shared G1
    wsplit_kernel<3><<<dim3(32, 32, 1), 256>>>(Ws2);                        // 11
    mgemm_kernel<1><<<dim3(8, NTOK / 128, 1), 256, SMEM_BYTES>>>(bs2, out); // 12 shared G2
    if (out_size > NTOK * DIM)
        lbl_kernel<<<1, 1>>>(out + (size_t)NTOK * DIM);                     // 13
    combine_kernel<<<(NTOK * D4 + 255) / 256, 256>>>(out);                  // 14
}